// round 17
// baseline (speedup 1.0000x reference)
#include <cuda_runtime.h>
#include <cuda_fp16.h>
#include <cstdint>
#include <cstddef>

// Problem shapes (fixed)
#define NROWS 32768
#define D_IN  1024
#define HID   1024
#define INTD  2048

// GEMM tiling: 128x256 CTA tile, 2x4 warps of 64x64, K-chunk 64 halfs.
// 1 CTA/SM (8 warps), 3-stage cp.async pipeline, one barrier per chunk,
// cross-chunk fragment pipelining. Crossbar: 176KB/chunk vs 192KB for the
// 2-CTA 128x128 config -> ~86 B/cyc at full tensor (was ~96).
#define BM 128
#define BN 256
#define BK 64
#define STAGES 3
#define ROWB 128                            // 64 halfs, no pad (XOR swizzle)
#define A_ST (BM * ROWB)                    // 16384
#define B_ST (BN * ROWB)                    // 32768
#define STAGE_BYTES (A_ST + B_ST)           // 49152
#define SMEM_DYN (STAGES * STAGE_BYTES)     // 147456
#define NTHR 256

// ---------------- scratch (device globals: allocation-free rule) ------------
__device__ int    g_cnt0, g_cnt1;
__device__ int    g_perm[NROWS];
__device__ __half g_xh [(size_t)NROWS * D_IN];
__device__ __half g_h1 [(size_t)NROWS * HID];
__device__ __half g_enc[(size_t)NROWS * INTD];
// Pre-transposed half weights: [n][k] K-major
__device__ __half g_Wt_e1[(size_t)2 * HID  * D_IN];
__device__ __half g_Wt_e2[(size_t)2 * INTD * HID ];
__device__ __half g_Wt_d1[(size_t)HID  * INTD];
__device__ __half g_Wt_d2[(size_t)D_IN * HID ];

// ---------------- helpers ----------------------------------------------------
__device__ __forceinline__ uint32_t smem_u32(const void* p) {
    uint32_t a;
    asm("{ .reg .u64 t; cvta.to.shared.u64 t, %1; cvt.u32.u64 %0, t; }" : "=r"(a) : "l"(p));
    return a;
}

#define CP_ASYNC16(dst, src, sz) \
    asm volatile("cp.async.cg.shared.global [%0], [%1], 16, %2;" \
                 :: "r"(dst), "l"(src), "r"(sz) : "memory")
#define CP_COMMIT() asm volatile("cp.async.commit_group;" ::: "memory")
#define CP_WAIT(n)  asm volatile("cp.async.wait_group %0;" :: "n"(n) : "memory")

#define LDSM_X4(r0, r1, r2, r3, addr) \
    asm volatile("ldmatrix.sync.aligned.m8n8.x4.shared.b16 {%0,%1,%2,%3}, [%4];" \
                 : "=r"(r0), "=r"(r1), "=r"(r2), "=r"(r3) : "r"(addr))

#define MMA16816(d, a, b0, b1) \
    asm volatile("mma.sync.aligned.m16n8k16.row.col.f32.f16.f16.f32 " \
                 "{%0,%1,%2,%3}, {%4,%5,%6,%7}, {%8,%9}, {%0,%1,%2,%3};" \
                 : "+f"((d)[0]), "+f"((d)[1]), "+f"((d)[2]), "+f"((d)[3]) \
                 : "r"((a)[0]), "r"((a)[1]), "r"((a)[2]), "r"((a)[3]), \
                   "r"(b0), "r"(b1))

// ---------------- routing ----------------------------------------------------
__global__ void build_perm_kernel(const int* __restrict__ lang, int n) {
    int i = blockIdx.x * blockDim.x + threadIdx.x;
    if (i < n) {
        if (lang[i] == 0) g_perm[atomicAdd(&g_cnt0, 1)] = i;
        else              g_perm[n - 1 - atomicAdd(&g_cnt1, 1)] = i;
    }
}

// ---------------- prep: ONE kernel for counters + f2h(x) + all transposes ----
#define TR_BLOCKS 9216
#define F2H_BLOCKS 16384            // 32768*1024 / 8 / 256
__global__ void prep_all_kernel(
    const float* __restrict__ x, __half* __restrict__ xh,
    const float* __restrict__ W_de1, const float* __restrict__ W_nl1,
    const float* __restrict__ W_de2, const float* __restrict__ W_nl2,
    const float* __restrict__ W_d1,  const float* __restrict__ W_d2,
    __half* __restrict__ Wt_e1, __half* __restrict__ Wt_e2,
    __half* __restrict__ Wt_d1, __half* __restrict__ Wt_d2)
{
    const int bid = blockIdx.x;
    const int tid = threadIdx.x;
    if (bid == 0 && tid == 0) { g_cnt0 = 0; g_cnt1 = 0; }

    if (bid >= TR_BLOCKS) {
        int i = ((bid - TR_BLOCKS) * 256 + tid) * 8;
        float4 a = *(const float4*)(x + i);
        float4 b = *(const float4*)(x + i + 4);
        __half h[8];
        h[0] = __float2half_rn(a.x); h[1] = __float2half_rn(a.y);
        h[2] = __float2half_rn(a.z); h[3] = __float2half_rn(a.w);
        h[4] = __float2half_rn(b.x); h[5] = __float2half_rn(b.y);
        h[6] = __float2half_rn(b.z); h[7] = __float2half_rn(b.w);
        *(uint4*)(xh + i) = *(const uint4*)h;
        return;
    }

    const float* in; __half* out; int K, N, tile;
    if      (bid < 1024) { in = W_de1; out = Wt_e1;                      K = 1024; N = 1024; tile = bid; }
    else if (bid < 2048) { in = W_nl1; out = Wt_e1 + (size_t)HID * D_IN; K = 1024; N = 1024; tile = bid - 1024; }
    else if (bid < 4096) { in = W_de2; out = Wt_e2;                      K = 1024; N = 2048; tile = bid - 2048; }
    else if (bid < 6144) { in = W_nl2; out = Wt_e2 + (size_t)INTD * HID; K = 1024; N = 2048; tile = bid - 4096; }
    else if (bid < 8192) { in = W_d1;  out = Wt_d1;                      K = 2048; N = 1024; tile = bid - 6144; }
    else                 { in = W_d2;  out = Wt_d2;                      K = 1024; N = 1024; tile = bid - 8192; }

    __shared__ float t[32][33];
    const int tx = tid & 31;
    const int ty = tid >> 5;
    const int ntx = N / 32;
    const int n0 = (tile % ntx) * 32;
    const int k0 = (tile / ntx) * 32;
    #pragma unroll
    for (int j = ty; j < 32; j += 8)
        t[j][tx] = in[(size_t)(k0 + j) * N + n0 + tx];
    __syncthreads();
    #pragma unroll
    for (int j = ty; j < 32; j += 8)
        out[(size_t)(n0 + j) * K + k0 + tx] = __float2half_rn(t[tx][j]);
}

// ---------------- fp16 tensor-core GEMM --------------------------------------
// C[M,N] = act(A @ Bt^T + bias). A: [M,K] half. Bt: [N,K] half (K-major).
// 128x256 CTA tile, 8 warps (2x4 of 64x64), 3-stage pipeline:
//   prologue: issue(0), issue(1); wait stage0; preload frags(chunk0, kh0)
//   iter i:   CP_WAIT(0) [stages i, i+1 ready]; bar; issue(i+2)
//             kh=0..2: prefetch frags kh+1; MMA kh
//             kh=3:    prefetch frags chunk i+1 kh0 (stage (i+1)%3); MMA
template<bool RELU, bool GATHER, bool SCATTER, bool SPLIT, bool OUT_HALF>
__global__ void __launch_bounds__(NTHR, 1)
moe_gemm_h(const __half* __restrict__ A,
           const __half* __restrict__ Bt0, const __half* __restrict__ Bt1,
           const float* __restrict__ bias0, const float* __restrict__ bias1,
           void* __restrict__ Cv, int M, int N, int K)
{
    const int n0 = SPLIT ? g_cnt0 : M;
    const int e  = SPLIT ? (int)blockIdx.z : 0;
    const int lo = (e == 0) ? 0  : n0;
    const int hi = (e == 0) ? n0 : M;
    const int row0 = blockIdx.y * BM;
    if (SPLIT && (row0 >= hi || row0 + BM <= lo)) return;
    const int col0 = blockIdx.x * BN;

    const __half* __restrict__ Bt   = (e == 0) ? Bt0   : Bt1;
    const float*  __restrict__ bias = (e == 0) ? bias0 : bias1;

    extern __shared__ char smem[];
    const uint32_t sbase = smem_u32(smem);

    const int tid  = threadIdx.x;
    const int warp = tid >> 5;
    const int lane = tid & 31;
    const int warpM = warp >> 2;      // 0..1 (64 rows)
    const int warpN = warp & 3;       // 0..3 (64 cols)
    const int g  = lane >> 2;         // 0..7
    const int tg = lane & 3;          // 0..3

    // ---- fill addressing: strided slots, minimal register state -------------
    // thread -> base row r0 = tid>>3 (0..31), granule gr0 = tid&7.
    // Slots stride +32 rows: (r&7) invariant, so dst strides by 32*ROWB = 4096
    // with a fixed swizzle. A: 4 slots (128 rows). B: 8 slots (256 rows).
    const int r0  = tid >> 3;         // 0..31
    const int gr0 = tid & 7;          // 0..7
    const uint32_t dstSwz = (uint32_t)(r0 * ROWB + ((gr0 ^ (r0 & 7)) * 16));
    const uint32_t aDst0 = sbase + dstSwz;
    const uint32_t bDst0 = sbase + A_ST + dstSwz;
    const size_t rowStride = (size_t)32 * K;   // halfs between slots

    const __half* aSrcArr[4];                  // only materialized when GATHER
    if (GATHER) {
        #pragma unroll
        for (int s = 0; s < 4; s++) {
            int m = row0 + r0 + 32 * s;
            bool v = (!SPLIT) || (m >= lo && m < hi);
            aSrcArr[s] = A + (size_t)(v ? g_perm[m] : 0) * K + gr0 * 8;
        }
    }
    const __half* aSrc0 = A  + (size_t)(row0 + r0) * K + gr0 * 8;
    const __half* bSrc0 = Bt + (size_t)(col0 + r0) * K + gr0 * 8;

    const int nch = K / BK;

    auto issue_all = [&](int c) {
        const uint32_t so = (uint32_t)((c % STAGES) * STAGE_BYTES);
        const int ko = c * BK;
        #pragma unroll
        for (int s = 0; s < 4; s++) {
            uint32_t sz = 16u;
            if (SPLIT) {
                int m = row0 + r0 + 32 * s;
                sz = (m >= lo && m < hi) ? 16u : 0u;
            }
            const __half* src = GATHER ? (aSrcArr[s] + ko)
                                       : (aSrc0 + ko + s * rowStride);
            CP_ASYNC16(aDst0 + so + s * 4096u, src, sz);
        }
        #pragma unroll
        for (int s = 0; s < 8; s++)
            CP_ASYNC16(bDst0 + so + s * 4096u, bSrc0 + ko + s * rowStride, 16u);
        CP_COMMIT();
    };

    float acc[4][8][4];
    #pragma unroll
    for (int mt = 0; mt < 4; mt++)
        #pragma unroll
        for (int nt = 0; nt < 8; nt++)
            #pragma unroll
            for (int i = 0; i < 4; i++) acc[mt][nt][i] = 0.0f;

    // per-warp ldmatrix row bases + swizzle masks
    uint32_t aRowOff[4]; int aRm[4];
    #pragma unroll
    for (int mt = 0; mt < 4; mt++) {
        int rr = warpM * 64 + mt * 16 + (lane & 15);
        aRowOff[mt] = sbase + (uint32_t)(rr * ROWB);
        aRm[mt] = rr & 7;
    }
    const int aChunk = lane >> 4;                 // 0..1
    uint32_t bRowOff[4]; int bRm[4];
    #pragma unroll
    for (int p = 0; p < 4; p++) {
        int rr = warpN * 64 + p * 16 + (lane & 7) + ((lane >> 4) << 3);
        bRowOff[p] = sbase + A_ST + (uint32_t)(rr * ROWB);
        bRm[p] = rr & 7;
    }
    const int bChunk = (lane >> 3) & 1;           // 0..1

    uint32_t af[2][4][4], bf[2][4][4];

    auto load_frags = [&](int buf, uint32_t so, int kh) {
        #pragma unroll
        for (int mt = 0; mt < 4; mt++) {
            uint32_t ad = aRowOff[mt] + so
                + (uint32_t)(((kh * 2 + aChunk) ^ aRm[mt]) * 16);
            LDSM_X4(af[buf][mt][0], af[buf][mt][1], af[buf][mt][2], af[buf][mt][3], ad);
        }
        #pragma unroll
        for (int p = 0; p < 4; p++) {
            uint32_t bd = bRowOff[p] + so
                + (uint32_t)(((kh * 2 + bChunk) ^ bRm[p]) * 16);
            LDSM_X4(bf[buf][p][0], bf[buf][p][1], bf[buf][p][2], bf[buf][p][3], bd);
        }
    };

    // ---- prologue ----
    issue_all(0);
    issue_all(1);
    CP_WAIT(1);                  // stage 0 complete
    __syncthreads();
    load_frags(0, 0u, 0);        // chunk 0, kh 0 -> buf 0

    for (int i = 0; i < nch; i++) {
        CP_WAIT(0);              // all groups <= i+1 done: stages i, i+1 ready
        __syncthreads();
        if (i + 2 < nch) issue_all(i + 2);   // into stage (i-1)%3, freed above

        const uint32_t so  = (uint32_t)((i % STAGES) * STAGE_BYTES);
        const uint32_t son = (uint32_t)(((i + 1) % STAGES) * STAGE_BYTES);
        #pragma unroll
        for (int kh = 0; kh < 4; kh++) {
            const int cur = kh & 1;
            if (kh < 3)             load_frags(cur ^ 1, so,  kh + 1);
            else if (i + 1 < nch)   load_frags(cur ^ 1, son, 0);   // cross-chunk
            #pragma unroll
            for (int mt = 0; mt < 4; mt++)
                #pragma unroll
                for (int nt = 0; nt < 8; nt++)
                    MMA16816(acc[mt][nt], af[cur][mt],
                             bf[cur][nt >> 1][(nt & 1) * 2],
                             bf[cur][nt >> 1][(nt & 1) * 2 + 1]);
        }
    }

    // ---- epilogue ----
    #pragma unroll
    for (int mt = 0; mt < 4; mt++) {
        const int mBase = row0 + warpM * 64 + mt * 16 + g;
        #pragma unroll
        for (int nt = 0; nt < 8; nt++) {
            const int c = col0 + warpN * 64 + nt * 8 + 2 * tg;
            const float bv0 = bias[c];
            const float bv1 = bias[c + 1];
            #pragma unroll
            for (int half_i = 0; half_i < 2; half_i++) {
                const int m = mBase + half_i * 8;
                if (SPLIT && (m < lo || m >= hi)) continue;
                float v0 = acc[mt][nt][half_i * 2 + 0] + bv0;
                float v1 = acc[mt][nt][half_i * 2 + 1] + bv1;
                if (RELU) { v0 = fmaxf(v0, 0.f); v1 = fmaxf(v1, 0.f); }
                const int mo = SCATTER ? g_perm[m] : m;
                if (OUT_HALF) {
                    __half2 hv;
                    hv.x = __float2half_rn(v0);
                    hv.y = __float2half_rn(v1);
                    *(__half2*)((__half*)Cv + (size_t)mo * N + c) = hv;
                } else {
                    *(float2*)((float*)Cv + (size_t)mo * N + c) = make_float2(v0, v1);
                }
            }
        }
    }
}

// ---------------- launch ------------------------------------------------------
extern "C" void kernel_launch(void* const* d_in, const int* in_sizes, int n_in,
                              void* d_out, int out_size)
{
    const float* x     = (const float*)d_in[0];
    const int*   lang  = (const int*)  d_in[1];
    const float* W_de1 = (const float*)d_in[2];
    const float* b_de1 = (const float*)d_in[3];
    const float* W_de2 = (const float*)d_in[4];
    const float* b_de2 = (const float*)d_in[5];
    const float* W_nl1 = (const float*)d_in[6];
    const float* b_nl1 = (const float*)d_in[7];
    const float* W_nl2 = (const float*)d_in[8];
    const float* b_nl2 = (const float*)d_in[9];
    const float* W_d1  = (const float*)d_in[10];
    const float* b_d1  = (const float*)d_in[11];
    const float* W_d2  = (const float*)d_in[12];
    const float* b_d2  = (const float*)d_in[13];
    float* out = (float*)d_out;

    const int M = in_sizes[1];  // 32768

    __half *xh, *h1, *enc, *Wt_e1, *Wt_e2, *Wt_d1, *Wt_d2;
    cudaGetSymbolAddress((void**)&xh,    g_xh);
    cudaGetSymbolAddress((void**)&h1,    g_h1);
    cudaGetSymbolAddress((void**)&enc,   g_enc);
    cudaGetSymbolAddress((void**)&Wt_e1, g_Wt_e1);
    cudaGetSymbolAddress((void**)&Wt_e2, g_Wt_e2);
    cudaGetSymbolAddress((void**)&Wt_d1, g_Wt_d1);
    cudaGetSymbolAddress((void**)&Wt_d2, g_Wt_d2);

    cudaFuncSetAttribute(moe_gemm_h<true,  true,  false, true,  true >,
                         cudaFuncAttributeMaxDynamicSharedMemorySize, SMEM_DYN);
    cudaFuncSetAttribute(moe_gemm_h<false, false, false, true,  true >,
                         cudaFuncAttributeMaxDynamicSharedMemorySize, SMEM_DYN);
    cudaFuncSetAttribute(moe_gemm_h<true,  false, false, false, true >,
                         cudaFuncAttributeMaxDynamicSharedMemorySize, SMEM_DYN);
    cudaFuncSetAttribute(moe_gemm_h<false, false, true,  false, false>,
                         cudaFuncAttributeMaxDynamicSharedMemorySize, SMEM_DYN);

    // Launch order (profiler captures our launch index 3):
    //   0 = prep_all, 1 = build_perm, 2 = L1, 3 = L2 <-- ncu, 4 = L3, 5 = L4
    prep_all_kernel<<<TR_BLOCKS + F2H_BLOCKS, 256>>>(
        x, xh, W_de1, W_nl1, W_de2, W_nl2, W_d1, W_d2,
        Wt_e1, Wt_e2, Wt_d1, Wt_d2);
    build_perm_kernel<<<(M + 255) / 256, 256>>>(lang, M);

    // L1: h1 = relu(x[perm] @ W1_e + b1_e)   [split, gather]
    moe_gemm_h<true, true, false, true, true>
        <<<dim3(HID / BN, M / BM, 2), NTHR, SMEM_DYN>>>(
        xh, Wt_e1, Wt_e1 + (size_t)HID * D_IN, b_de1, b_nl1, h1, M, HID, D_IN);

    // L2: enc = h1 @ W2_e + b2_e             [split]
    moe_gemm_h<false, false, false, true, true>
        <<<dim3(INTD / BN, M / BM, 2), NTHR, SMEM_DYN>>>(
        h1, Wt_e2, Wt_e2 + (size_t)INTD * HID, b_de2, b_nl2, enc, M, INTD, HID);

    // L3: h1 = relu(enc @ W_d1 + b_d1)       [shared decoder]
    moe_gemm_h<true, false, false, false, true>
        <<<dim3(HID / BN, M / BM, 1), NTHR, SMEM_DYN>>>(
        enc, Wt_d1, Wt_d1, b_d1, b_d1, h1, M, HID, INTD);

    // L4: out[perm] = h1 @ W_d2 + b_d2       [scatter, f32 out]
    moe_gemm_h<false, false, true, false, false>
        <<<dim3(D_IN / BN, M / BM, 1), NTHR, SMEM_DYN>>>(
        h1, Wt_d2, Wt_d2, b_d2, b_d2, out, M, D_IN, HID);
}